// round 9
// baseline (speedup 1.0000x reference)
#include <cuda_runtime.h>
#include <math.h>
#include <stdint.h>

#define NZ 1024
#define NX 4096
#define K_CTAS 64
#define ROWS_PER_CTA 16          /* NZ / K_CTAS */
#define THREADS 512              /* one warp per row */
#define LOG_C 8.31776616671934f  /* 12 * ln(2): per-step 2^12 compensation */

// Persistent device scratch (allocation-free). Tagged ping-pong buffers:
// g_vt[b][row] = { float_bits(v), tag } ; tag = t+1 for the step that wrote it.
__device__ __align__(16) uint2 g_vt[2][NZ];

// ---------------------------------------------------------------------------
__device__ __forceinline__ void st_tagged(uint2* p, float v, unsigned tag) {
    asm volatile("st.global.cg.v2.u32 [%0], {%1,%2};"
                 :: "l"(p), "r"(__float_as_uint(v)), "r"(tag) : "memory");
}
__device__ __forceinline__ uint4 ld_tagged2(const uint4* p) {
    uint4 r;
    asm volatile("ld.global.cg.v4.u32 {%0,%1,%2,%3}, [%4];"
                 : "=r"(r.x), "=r"(r.y), "=r"(r.z), "=r"(r.w) : "l"(p) : "memory");
    return r;
}
__device__ __forceinline__ float warp_sum(float v) {
    #pragma unroll
    for (int o = 16; o; o >>= 1) v += __shfl_xor_sync(0xffffffffu, v, o);
    return v;
}

// ---------------------------------------------------------------------------
// Persistent forward kernel. 64 CTAs, 512 threads (16 warps, one row each).
// Warp w of CTA c owns row i = c*16 + w; the normalized A-row lives in
// registers: lane l holds columns {128k + 4l .. +3}, k = 0..7.
//
// Scaled recurrence (no per-step normalization needed):
//   e[i][t]   = B[i, obs_t] * 4096 / rowsumB[i]
//   v_0[i]    = (pi_i/sumPi) * e[i][0] * 2^-12      ( = p_0[i] exactly )
//   v_t       = (A_hat v_{t-1}) o e[.][t]           ( = p_t * 4096^t )
//   alpha_t[i]= log(v_t[i]) - t * 12 ln 2
// Sum(v_t) random-walks (sigma ~2 nats over 4096 steps) around 2^-12;
// entries stay far inside fp32 range; accumulated fp32 drift ~1e-4 nats.
//
// Sync: each published v word carries its step tag; consumers poll the data
// words directly (single L2 round trip, no counter, no atomics). Ping-pong
// reuse is safe: a tag-(t+1) publish sits after the CTA's one per-step
// __syncthreads, ordering it behind ALL 1024 tag-t poll loads (whose data
// has been consumed into smem by barrier time); observing every tag-(t+1)
// word therefore proves all CTAs retired their reads of the buffer that
// step t+1 overwrites. Across graph replays the only stale-tag match is at
// t=4095 against the previous replay's bit-identical v_4094 -> benign.
// First execution sees zero-initialized tags.
//
// Locality: each CTA's 16 rows occupy exactly one 128B L2 line of g_vt, so
// its 16 publishes coalesce and every 16B poll word is written by one CTA.
//
// SMEM staging is double-buffered so ONE barrier per step suffices: reads of
// a buffer at step t are separated from that buffer's overwrite at step t+2
// by the intervening barrier at step t+1.
// ---------------------------------------------------------------------------
__global__ void __launch_bounds__(THREADS, 1)
hmm_forward_persistent(const int*   __restrict__ obs,
                       const float* __restrict__ pi,
                       const float* __restrict__ A,
                       const float* __restrict__ B,
                       float*       __restrict__ out) {
    __shared__ float vs[2][NZ];    // double-buffered staged v (8KB)
    __shared__ int   obs_s[NX];    // observations (16KB)
    __shared__ float sp_s;         // sum(pi)

    const int tid = threadIdx.x;
    const int w   = tid >> 5;
    const int l   = tid & 31;
    const int i   = blockIdx.x * ROWS_PER_CTA + w;   // this warp's row
    const float* Bi = B + (size_t)i * NX;            // this row of B
    float*       Oi = out + (size_t)i * NX;          // this row of out

    // stage observations once (removes per-step dependent LDG)
    {
        const int4* o4 = reinterpret_cast<const int4*>(obs);
        int4* s4 = reinterpret_cast<int4*>(obs_s);
        #pragma unroll
        for (int k = 0; k < NX / 4 / THREADS; k++)       // 2 iters
            s4[tid + k * THREADS] = o4[tid + k * THREADS];
    }

    // ---- load + row-normalize this warp's A row into registers ----
    float4 a_reg[8];
    {
        const float4* Arow = reinterpret_cast<const float4*>(A + (size_t)i * NZ);
        float s = 0.f;
        #pragma unroll
        for (int k = 0; k < 8; k++) {
            float4 x = Arow[32 * k + l];
            a_reg[k] = x;
            s += (x.x + x.y) + (x.z + x.w);
        }
        s = warp_sum(s);
        const float rcp = 1.0f / s;
        #pragma unroll
        for (int k = 0; k < 8; k++) {
            a_reg[k].x *= rcp; a_reg[k].y *= rcp;
            a_reg[k].z *= rcp; a_reg[k].w *= rcp;
        }
    }

    // ---- B row sum -> per-warp scale rb = 4096 / rowsumB[i] ----
    float rb;
    {
        const float4* Brow = reinterpret_cast<const float4*>(Bi);
        float s = 0.f;
        #pragma unroll
        for (int c = 0; c < 32; c++) {
            float4 x = Brow[32 * c + l];
            s += (x.x + x.y) + (x.z + x.w);
        }
        rb = 4096.0f / warp_sum(s);   // all lanes hold rb
    }

    // ---- sum(pi) by warp 0 (fixed order, identical in every CTA) ----
    if (w == 0) {
        float s = 0.f;
        #pragma unroll
        for (int k = 0; k < 32; k++) s += pi[32 * k + l];
        s = warp_sum(s);
        if (l == 0) sp_s = s;
    }
    __syncthreads();   // obs_s, sp_s ready

    // ---- step 0: publish v_0 with tag 1 ----
    if (l == 0) {
        const float pn = pi[i] / sp_s;
        const float e0 = __ldg(&Bi[obs_s[0]]) * rb;
        const float v0 = pn * e0 * 0.000244140625f;          // * 2^-12
        st_tagged(&g_vt[0][i], v0, 1u);
        Oi[0] = __logf(v0);
    }
    // converged prefetch: every lane issues the same load (1 L1 transaction)
    float er = __ldg(&Bi[obs_s[1]]) * rb;   // scaled emission for t=1

    // one step of the recurrence: poll tag t, dot, publish tag t+1.
    // 'prefetch' = whether to fetch next emission inside the step.
    auto do_step = [&](int t, bool prefetch) {
        const unsigned tag = (unsigned)t;                     // written at t-1
        const int      b   = (t - 1) & 1;
        // thread tid polls rows {2*tid, 2*tid+1}: one 16B load, each 8B half
        // a consistent (bits, tag) atom.
        const uint4* p0 = reinterpret_cast<const uint4*>(g_vt[b]) + tid;

        uint4 pa;
        do { pa = ld_tagged2(p0); } while (pa.y != tag || pa.w != tag);

        // stage into this step's smem buffer
        reinterpret_cast<float2*>(vs[b])[tid] =
            make_float2(__uint_as_float(pa.x), __uint_as_float(pa.z));
        __syncthreads();   // the only barrier: all 1024 words staged

        // d_i = <Ahat_row_i, v>  (A in regs, conflict-free LDS.128)
        const float4* vs4 = reinterpret_cast<const float4*>(vs[b]);
        float4 acc = make_float4(0.f, 0.f, 0.f, 0.f);
        #pragma unroll
        for (int k = 0; k < 8; k++) {
            float4 vv = vs4[32 * k + l];
            acc.x = fmaf(a_reg[k].x, vv.x, acc.x);
            acc.y = fmaf(a_reg[k].y, vv.y, acc.y);
            acc.z = fmaf(a_reg[k].z, vv.z, acc.z);
            acc.w = fmaf(a_reg[k].w, vv.w, acc.w);
        }
        const float d = warp_sum((acc.x + acc.y) + (acc.z + acc.w));

        // all lanes hold d and er; publisher does ONLY the store
        const float g = d * er;                               // v_t[i]
        if (l == 0)
            st_tagged(&g_vt[t & 1][i], g, (unsigned)(t + 1)); // publish ASAP
        if (l == 1)
            Oi[t] = __logf(g) - (float)t * LOG_C;             // off crit path

        if (prefetch)   // converged prefetch of next scaled emission
            er = __ldg(&Bi[obs_s[t + 1]]) * rb;
    };

    // ---- main scan: 4094 full steps + peeled last step ----
    #pragma unroll 2
    for (int t = 1; t < NX - 1; ++t) do_step(t, true);
    do_step(NX - 1, false);
}

// ---------------------------------------------------------------------------
// Inputs (metadata order): obs int32[4096], start_prob f32[1024],
// transition f32[1024*1024], emission f32[1024*4096]. Output f32[1024,4096].
// ---------------------------------------------------------------------------
extern "C" void kernel_launch(void* const* d_in, const int* in_sizes, int n_in,
                              void* d_out, int out_size) {
    const int*   obs = (const int*)d_in[0];
    const float* pi  = (const float*)d_in[1];
    const float* A   = (const float*)d_in[2];
    const float* B   = (const float*)d_in[3];
    float*       out = (float*)d_out;

    hmm_forward_persistent<<<K_CTAS, THREADS>>>(obs, pi, A, B, out);
}